// round 13
// baseline (speedup 1.0000x reference)
#include <cuda_runtime.h>
#include <cuda_fp16.h>
#include <cstdint>

// ---------------- problem constants ----------------
#define BATCH 4096
#define NOBST 128
#define VEH   18
#define H     256
#define OBSF  138
#define KC    64            // K per chunk
#define NCHUNK 4            // 256/64
#define LDAH  72            // halves per A row (144B pitch: ldmatrix conflict-free)
#define LDBH  72

__device__ __half g_ow2T[H * H];        // ow2 transposed [n][k], half
__device__ float  g_pooled[BATCH * H];  // encoder -> Q-head scratch

typedef unsigned long long ull;

// ---------------- encoder smem (~120 KB) ----------------
struct EncSmem {
    __half Ah[2][NOBST * LDAH];   // 2 x 18432 B : h1 chunk double-buffer
    __half Bh[2][H * LDBH];       // 2 x 36864 B : ow2T chunk double-buffer
    float4 obst4[NOBST];
    float  masks[NOBST];
    float  base[H];
    float4 w4[H];
    float  ob2s[H];
    float  pooled_s[H];
    float  veh[24];
};

// ---------------- Q-head smem ----------------
#define R2  32
#define CLD 36
struct QSmem {
    float combT[396 * CLD];
    float q1T[H * CLD];
    float wpart[8 * R2];
};

// ---------------- helpers ----------------
__device__ __forceinline__ uint32_t smaddr(const void* p) {
    return (uint32_t)__cvta_generic_to_shared(p);
}
__device__ __forceinline__ void ldsm4(uint32_t& r0, uint32_t& r1,
                                      uint32_t& r2, uint32_t& r3, uint32_t addr) {
    asm volatile("ldmatrix.sync.aligned.m8n8.x4.shared.b16 {%0,%1,%2,%3}, [%4];"
                 : "=r"(r0), "=r"(r1), "=r"(r2), "=r"(r3) : "r"(addr));
}
__device__ __forceinline__ void mma16816(float* c,
    uint32_t a0, uint32_t a1, uint32_t a2, uint32_t a3,
    uint32_t b0, uint32_t b1)
{
    asm volatile(
        "mma.sync.aligned.m16n8k16.row.col.f32.f16.f16.f32 "
        "{%0,%1,%2,%3}, {%4,%5,%6,%7}, {%8,%9}, {%0,%1,%2,%3};"
        : "+f"(c[0]), "+f"(c[1]), "+f"(c[2]), "+f"(c[3])
        : "r"(a0), "r"(a1), "r"(a2), "r"(a3), "r"(b0), "r"(b1));
}
__device__ __forceinline__ ull pack2(float x, float y) {
    ull r; asm("mov.b64 %0, {%1, %2};" : "=l"(r) : "f"(x), "f"(y)); return r;
}
__device__ __forceinline__ void unpack2(float &x, float &y, ull v) {
    asm("mov.b64 {%0, %1}, %2;" : "=f"(x), "=f"(y) : "l"(v));
}
__device__ __forceinline__ void fma2(ull &d, ull a, ull b) {
    asm("fma.rn.f32x2 %0, %1, %2, %0;" : "+l"(d) : "l"(a), "l"(b));
}

// ---------------- prep: transpose ow2 -> half [n][k] ----------------
__global__ void prep_ow2(const float* __restrict__ ow2) {
    __shared__ float tile[32][33];
    const int tx = threadIdx.x, ty = threadIdx.y;
    const int kt = blockIdx.y * 32, nt = blockIdx.x * 32;
    #pragma unroll
    for (int i = 0; i < 4; i++)
        tile[ty + 8 * i][tx] = ow2[(kt + ty + 8 * i) * H + nt + tx];
    __syncthreads();
    #pragma unroll
    for (int i = 0; i < 4; i++)
        g_ow2T[(nt + ty + 8 * i) * H + kt + tx] = __float2half(tile[tx][ty + 8 * i]);
}

// ---------------- encoder: 1 CTA (1024 thr / 32 warps) per batch row ----------------
// produce A chunk: thread covers channel pair (c0,c0+1), 4 m-rows (warp = m-group)
__device__ __forceinline__ void produce_chunk(EncSmem* S, int chunk, int buf,
                                              int t, int w) {
    const int c0 = chunk * KC + (t & 31) * 2;
    const float b0v = S->base[c0],  b1v = S->base[c0 + 1];
    const float4 w0 = S->w4[c0];
    const float4 w1 = S->w4[c0 + 1];
    __half* dst = S->Ah[buf] + (t & 31) * 2 - chunk * KC;   // column base
    #pragma unroll
    for (int mi = 0; mi < 4; mi++) {
        const int m = w * 4 + mi;
        float4 o = S->obst4[m];          // warp-broadcast
        float v0 = b0v, v1 = b1v;
        v0 = fmaf(w0.x, o.x, v0);  v1 = fmaf(w1.x, o.x, v1);
        v0 = fmaf(w0.y, o.y, v0);  v1 = fmaf(w1.y, o.y, v1);
        v0 = fmaf(w0.z, o.z, v0);  v1 = fmaf(w1.z, o.z, v1);
        v0 = fmaf(w0.w, o.w, v0);  v1 = fmaf(w1.w, o.w, v1);
        *(__half2*)(S->Ah[buf] + m * LDAH + (t & 31) * 2) =
            __floats2half2_rn(fmaxf(v0, 0.f), fmaxf(v1, 0.f));
    }
    (void)dst;
}

__global__ __launch_bounds__(1024, 1)
void setq_enc(const float* __restrict__ obs,
              const float* __restrict__ obstacles,
              const float* __restrict__ ow1,
              const float* __restrict__ ob1,
              const float* __restrict__ ob2)
{
    extern __shared__ char smraw[];
    EncSmem* S = (EncSmem*)smraw;
    const int b = blockIdx.x;
    const int t = threadIdx.x;
    const int w = t >> 5, lane = t & 31;

    // ---- stage per-batch scalars ----
    if (t < VEH) S->veh[t] = obs[b * OBSF + t];
    if (t >= 128 && t < 256) S->masks[t - 128] = obstacles[(b * 5 + 4) * NOBST + (t - 128)];
    if (t >= 256 && t < 512) { int c = t - 256; S->ob2s[c] = ob2[c]; S->pooled_s[c] = 0.f; }
    if (t < 512) { int j = t >> 7, m = t & 127;
        ((float*)&S->obst4[m])[j] = obstacles[(b * 5 + j) * NOBST + m]; }
    __syncthreads();

    // ---- hoisted vehicle part per channel; B chunk0 stage ----
    if (t < H) {
        float bb = ob1[t];
        #pragma unroll
        for (int f = 0; f < VEH; f++)
            bb = fmaf(S->veh[f], ow1[f * H + t], bb);
        S->base[t] = bb;
        S->w4[t] = make_float4(ow1[18 * H + t], ow1[19 * H + t],
                               ow1[20 * H + t], ow1[21 * H + t]);
    }
    {   // B chunk0: 256 rows x 64 halves; thread: row t>>2, 32B part (t&3)
        const int n = t >> 2, p = t & 3;
        const uint4* src = (const uint4*)(g_ow2T + n * H + 0 * KC + p * 16);
        uint4* dst = (uint4*)(S->Bh[0] + n * LDBH + p * 16);
        dst[0] = src[0];
        dst[1] = src[1];
    }
    __syncthreads();     // base visible

    produce_chunk(S, 0, 0, t, w);
    __syncthreads();

    // ---- GEMM: D[m=128][n=256], warp tile m16 x n64, 32 warps ----
    const int m0 = (w & 7) * 16;
    const int nq = (w >> 3) * 64;
    const int r  = lane >> 2;
    const int q  = lane & 3;

    float acc[32];
    #pragma unroll
    for (int i = 0; i < 32; i++) acc[i] = 0.f;

    const uint32_t a_lane = smaddr(S->Ah[0]) +
        (uint32_t)(((m0 + (lane & 15)) * LDAH + (lane >> 4) * 8) * 2);
    const uint32_t b_lane = smaddr(S->Bh[0]) +
        (uint32_t)(((nq + 8 * (lane >> 4) + (lane & 7)) * LDBH + ((lane >> 3) & 1) * 8) * 2);
    const uint32_t ABUF = NOBST * LDAH * 2;   // 18432 B
    const uint32_t BBUF = H * LDBH * 2;       // 36864 B

    for (int kc = 0; kc < NCHUNK; kc++) {
        const int bi = kc & 1;
        uint4 p0, p1;
        if (kc < NCHUNK - 1) {   // prefetch next B chunk into regs
            const __half* src = g_ow2T + (t >> 2) * H + (kc + 1) * KC + (t & 3) * 16;
            p0 = ((const uint4*)src)[0];
            p1 = ((const uint4*)src)[1];
        }
        const uint32_t aA = a_lane + bi * ABUF;
        const uint32_t aB = b_lane + bi * BBUF;
        #pragma unroll
        for (int ks = 0; ks < 4; ks++) {
            const uint32_t koff = ks * 32;       // 16 halves
            uint32_t a0, a1, a2, a3;
            ldsm4(a0, a1, a2, a3, aA + koff);
            #pragma unroll
            for (int j2 = 0; j2 < 4; j2++) {
                uint32_t b0, b1, b2, b3;
                ldsm4(b0, b1, b2, b3, aB + j2 * (16 * LDBH * 2) + koff);
                mma16816(acc + (2 * j2) * 4,     a0, a1, a2, a3, b0, b1);
                mma16816(acc + (2 * j2 + 1) * 4, a0, a1, a2, a3, b2, b3);
            }
        }
        if (kc < NCHUNK - 1) {
            const int nb = bi ^ 1;
            produce_chunk(S, kc + 1, nb, t, w);
            uint4* dst = (uint4*)(S->Bh[nb] + (t >> 2) * LDBH + (t & 3) * 16);
            dst[0] = p0;
            dst[1] = p1;
        }
        __syncthreads();
    }

    // ---- epilogue: bias + relu + masked pool ----
    {
        const float mk0 = S->masks[m0 + r];
        const float mk1 = S->masks[m0 + r + 8];
        #pragma unroll
        for (int j = 0; j < 8; j++) {
            const int n = nq + 8 * j + 2 * q;
            const float o0 = S->ob2s[n], o1 = S->ob2s[n + 1];
            const float* cp = acc + j * 4;
            float v0 = mk0 * fmaxf(cp[0] + o0, 0.f) + mk1 * fmaxf(cp[2] + o0, 0.f);
            float v1 = mk0 * fmaxf(cp[1] + o1, 0.f) + mk1 * fmaxf(cp[3] + o1, 0.f);
            #pragma unroll
            for (int o = 4; o <= 16; o <<= 1) {
                v0 += __shfl_xor_sync(0xffffffffu, v0, o);
                v1 += __shfl_xor_sync(0xffffffffu, v1, o);
            }
            if (lane < 4) {
                atomicAdd(&S->pooled_s[nq + 8 * j + 2 * lane],     v0);
                atomicAdd(&S->pooled_s[nq + 8 * j + 2 * lane + 1], v1);
            }
        }
    }
    __syncthreads();
    if (t < H) g_pooled[b * H + t] = S->pooled_s[t];
}

// ---------------- Q-head: batched, exact fp32, f32x2-packed ----------------
__global__ __launch_bounds__(256, 2)
void setq_qhead(const float* __restrict__ obs,
                const float* __restrict__ act,
                const float* __restrict__ qw1,
                const float* __restrict__ qb1,
                const float* __restrict__ qw2,
                const float* __restrict__ qb2,
                const float* __restrict__ qw3,
                const float* __restrict__ qb3,
                float* __restrict__ out)
{
    extern __shared__ char smraw[];
    QSmem* S = (QSmem*)smraw;
    const int rb = blockIdx.x * R2;
    const int t  = threadIdx.x;
    const int w  = t >> 5, lane = t & 31;

    {
        const int r = t >> 3, f0 = t & 7;
        for (int f = f0; f < OBSF; f += 8)
            S->combT[f * CLD + r] = obs[(rb + r) * OBSF + f];
        for (int c = f0; c < H; c += 8)
            S->combT[(OBSF + c) * CLD + r] = g_pooled[(rb + r) * H + c];
        if (f0 < 2)
            S->combT[(OBSF + H + f0) * CLD + r] = act[(rb + r) * 2 + f0];
    }
    __syncthreads();

    const int c = t;
    ull acc1[16];
    #pragma unroll
    for (int i = 0; i < 16; i++) acc1[i] = 0ULL;
    #pragma unroll 4
    for (int k = 0; k < 396; k++) {
        const ull wp = pack2(qw1[k * H + c], qw1[k * H + c]);
        const ulonglong2* row = (const ulonglong2*)(S->combT + k * CLD);
        #pragma unroll
        for (int u = 0; u < 8; u++) {
            ulonglong2 rr = row[u];
            fma2(acc1[2 * u],     rr.x, wp);
            fma2(acc1[2 * u + 1], rr.y, wp);
        }
    }
    {
        const float bias = qb1[c];
        #pragma unroll
        for (int i = 0; i < 16; i++) {
            float x, y;
            unpack2(x, y, acc1[i]);
            S->q1T[c * CLD + 2 * i]     = fmaxf(x + bias, 0.f);
            S->q1T[c * CLD + 2 * i + 1] = fmaxf(y + bias, 0.f);
        }
    }
    __syncthreads();

    ull acc2[16];
    #pragma unroll
    for (int i = 0; i < 16; i++) acc2[i] = 0ULL;
    #pragma unroll 4
    for (int k = 0; k < H; k++) {
        const ull wp = pack2(qw2[k * H + c], qw2[k * H + c]);
        const ulonglong2* row = (const ulonglong2*)(S->q1T + k * CLD);
        #pragma unroll
        for (int u = 0; u < 8; u++) {
            ulonglong2 rr = row[u];
            fma2(acc2[2 * u],     rr.x, wp);
            fma2(acc2[2 * u + 1], rr.y, wp);
        }
    }

    {
        const float qb2c = qb2[c], qw3c = qw3[c];
        float part[R2];
        #pragma unroll
        for (int i = 0; i < 16; i++) {
            float x, y;
            unpack2(x, y, acc2[i]);
            part[2 * i]     = fmaxf(x + qb2c, 0.f) * qw3c;
            part[2 * i + 1] = fmaxf(y + qb2c, 0.f) * qw3c;
        }
        #pragma unroll
        for (int o = 16; o > 0; o >>= 1) {
            #pragma unroll
            for (int i = 0; i < R2; i++)
                part[i] += __shfl_xor_sync(0xffffffffu, part[i], o);
        }
        if (lane == 0) {
            #pragma unroll
            for (int i = 0; i < R2; i++)
                S->wpart[w * R2 + i] = part[i];
        }
    }
    __syncthreads();
    if (t < R2) {
        float s = qb3[0];
        #pragma unroll
        for (int wi = 0; wi < 8; wi++) s += S->wpart[wi * R2 + t];
        out[rb + t] = s;
    }
}

extern "C" void kernel_launch(void* const* d_in, const int* in_sizes, int n_in,
                              void* d_out, int out_size)
{
    const float* obs       = (const float*)d_in[0];
    const float* obstacles = (const float*)d_in[1];
    const float* act       = (const float*)d_in[2];
    const float* ow1       = (const float*)d_in[3];
    const float* ob1       = (const float*)d_in[4];
    const float* ow2       = (const float*)d_in[5];
    const float* ob2       = (const float*)d_in[6];
    const float* qw1       = (const float*)d_in[7];
    const float* qb1       = (const float*)d_in[8];
    const float* qw2       = (const float*)d_in[9];
    const float* qb2       = (const float*)d_in[10];
    const float* qw3       = (const float*)d_in[11];
    const float* qb3       = (const float*)d_in[12];
    float* out             = (float*)d_out;

    cudaFuncSetAttribute(setq_enc,
                         cudaFuncAttributeMaxDynamicSharedMemorySize, (int)sizeof(EncSmem));
    cudaFuncSetAttribute(setq_qhead,
                         cudaFuncAttributeMaxDynamicSharedMemorySize, (int)sizeof(QSmem));

    prep_ow2<<<dim3(8, 8), dim3(32, 8)>>>(ow2);
    setq_enc<<<BATCH, 1024, sizeof(EncSmem)>>>(obs, obstacles, ow1, ob1, ob2);
    setq_qhead<<<BATCH / R2, 256, sizeof(QSmem)>>>(obs, act, qw1, qb1,
                                                   qw2, qb2, qw3, qb3, out);
}